// round 2
// baseline (speedup 1.0000x reference)
#include <cuda_runtime.h>
#include <math.h>

// Problem constants
#define BATCH 32
#define CH    256
#define HW    1024          // 32*32
#define NPIX  32768         // BATCH*HW
#define NPIXL 32768ULL

// ---------------- static device scratch (no allocations allowed) ----------------
__device__ float g_col3[2304ULL * NPIXL];   // im2col of x (3x3, pad1)      302 MB
__device__ float g_col2[2304ULL * NPIXL];   // im2col of out_sum (3x3,pad1) 302 MB
__device__ float g_cold[6400ULL * NPIXL];   // deform im2col (5x5)          839 MB
__device__ float g_osum[256ULL  * NPIXL];   // relu(bn(conv1)) += relu(bn(deform))
__device__ float g_offs[50ULL   * NPIXL];   // offset field [50][B*HW]

// ---------------- im2col for 3x3 / pad 1 ----------------
// dst[(c*9 + ky*3 + kx) * NPIX + n],  n = b*1024 + ho*32 + wo
// layout 0: src is NCHW x.  layout 1: src is [C][B*HW] (channel-major).
__global__ void im2col3_kernel(const float* __restrict__ src,
                               float* __restrict__ dst, int layout)
{
    size_t idx = (size_t)blockIdx.x * blockDim.x + threadIdx.x;
    if (idx >= 2304ULL * NPIXL) return;
    int row = (int)(idx >> 15);
    int n   = (int)(idx & 32767);
    int c = row / 9, t = row % 9;
    int ky = t / 3, kx = t % 3;
    int b = n >> 10, pix = n & 1023;
    int ho = pix >> 5, wo = pix & 31;
    int iy = ho + ky - 1, ix = wo + kx - 1;
    float v = 0.f;
    if ((unsigned)iy < 32u && (unsigned)ix < 32u) {
        size_t s = (layout == 0)
            ? (((size_t)(b * CH + c)) << 10) + (size_t)(iy * 32 + ix)
            : (((size_t)c) << 15) + (size_t)((b << 10) + iy * 32 + ix);
        v = src[s];
    }
    dst[idx] = v;
}

// ---------------- deformable bilinear sampling -> im2col (5x5, pad 2) ----------
// g_cold[(c*25 + k) * NPIX + n] = bilinear sample of x[b,c] at
//   (ho-2+i+dy, wo-2+j+dx) with zero outside borders (per-corner validity).
__global__ void deform_sample_kernel(const float* __restrict__ x)
{
    int b = blockIdx.x;          // 32
    int k = blockIdx.y;          // 25
    int i = k / 5, j = k % 5;
    int tid = threadIdx.x;       // 256
    const float* xb = x + (size_t)b * CH * HW;

    int   offn[4][4];
    float wgt [4][4];
    int   nn  [4];
    #pragma unroll
    for (int q = 0; q < 4; q++) {
        int p  = tid + q * 256;          // 0..1023
        int ho = p >> 5, wo = p & 31;
        int n  = (b << 10) + p;
        nn[q]  = n;
        float dy = g_offs[(size_t)(2 * k)     * NPIXL + n];
        float dx = g_offs[(size_t)(2 * k + 1) * NPIXL + n];
        float py = (float)(ho - 2 + i) + dy;
        float px = (float)(wo - 2 + j) + dx;
        float y0 = floorf(py), x0 = floorf(px);
        float wy1 = py - y0, wx1 = px - x0;
        float wy0 = 1.f - wy1, wx0 = 1.f - wx1;
        float ys[2]  = {y0, y0 + 1.f};
        float xs[2]  = {x0, x0 + 1.f};
        float wys[2] = {wy0, wy1};
        float wxs[2] = {wx0, wx1};
        #pragma unroll
        for (int cy = 0; cy < 2; cy++)
            #pragma unroll
            for (int cx = 0; cx < 2; cx++) {
                float yf = ys[cy], xf = xs[cx];
                bool valid = (yf >= 0.f) && (yf <= 31.f) && (xf >= 0.f) && (xf <= 31.f);
                int yc = (int)fminf(fmaxf(yf, 0.f), 31.f);
                int xc = (int)fminf(fmaxf(xf, 0.f), 31.f);
                offn[q][cy * 2 + cx] = yc * 32 + xc;
                wgt [q][cy * 2 + cx] = valid ? wys[cy] * wxs[cx] : 0.f;
            }
    }
    for (int c = 0; c < CH; c++) {
        const float* xc = xb + (size_t)c * HW;
        size_t drow = (size_t)(c * 25 + k) * NPIXL;
        #pragma unroll
        for (int q = 0; q < 4; q++) {
            float v = wgt[q][0] * xc[offn[q][0]] + wgt[q][1] * xc[offn[q][1]]
                    + wgt[q][2] * xc[offn[q][2]] + wgt[q][3] * xc[offn[q][3]];
            g_cold[drow + nn[q]] = v;
        }
    }
}

// ---------------- fused SGEMM: C[M,NPIX] = A[M,K] * B[K,NPIX] + epilogue ------
// mode 0: C = relu(bn(acc))                      (conv1 -> g_osum)
// mode 1: C = acc + bias[m]                      (offset conv -> g_offs)
// mode 2: C += relu(bn(acc))                     (deform conv accumulates g_osum)
// mode 3: out[b,m,pix] = relu(bn(acc) + x[b,m,pix])   (conv2 + residual)
__global__ __launch_bounds__(256, 2)
void gemm_kernel(const float* __restrict__ A, const float* __restrict__ B,
                 float* __restrict__ C, int M, int K, int mode,
                 const float* __restrict__ gg, const float* __restrict__ bb,
                 const float* __restrict__ mm, const float* __restrict__ vv,
                 const float* __restrict__ resid, float* __restrict__ outp)
{
    __shared__ float As[16][132];   // [k][m], padded
    __shared__ float Bs[16][128];   // [k][n]

    const int tid = threadIdx.x;
    const int m0  = blockIdx.y * 128;
    const int n0  = blockIdx.x * 128;
    const int tm  = tid >> 4;    // 0..15
    const int tn  = tid & 15;    // 0..15

    float acc[8][8];
    #pragma unroll
    for (int i = 0; i < 8; i++)
        #pragma unroll
        for (int j = 0; j < 8; j++) acc[i][j] = 0.f;

    float4 pa[2], pb[2];

    // --- load tile kt = 0 into regs ---
    #pragma unroll
    for (int r = 0; r < 2; r++) {
        int id = tid + r * 256;
        int row = id >> 2, c4 = id & 3;            // A: 128 rows x 4 float4
        if (m0 + row < M)
            pa[r] = *reinterpret_cast<const float4*>(&A[(size_t)(m0 + row) * K + c4 * 4]);
        else
            pa[r] = make_float4(0.f, 0.f, 0.f, 0.f);
        int brow = id >> 5, bc4 = id & 31;         // B: 16 rows x 32 float4
        pb[r] = *reinterpret_cast<const float4*>(&B[(size_t)brow * NPIXL + n0 + bc4 * 4]);
    }
    // store tile 0 to smem
    #pragma unroll
    for (int r = 0; r < 2; r++) {
        int id = tid + r * 256;
        int row = id >> 2, c4 = id & 3;
        As[c4 * 4 + 0][row] = pa[r].x;
        As[c4 * 4 + 1][row] = pa[r].y;
        As[c4 * 4 + 2][row] = pa[r].z;
        As[c4 * 4 + 3][row] = pa[r].w;
        int brow = id >> 5, bc4 = id & 31;
        *reinterpret_cast<float4*>(&Bs[brow][bc4 * 4]) = pb[r];
    }
    __syncthreads();

    for (int kt = 0; kt < K; kt += 16) {
        bool has_next = (kt + 16) < K;
        if (has_next) {
            int kn = kt + 16;
            #pragma unroll
            for (int r = 0; r < 2; r++) {
                int id = tid + r * 256;
                int row = id >> 2, c4 = id & 3;
                if (m0 + row < M)
                    pa[r] = *reinterpret_cast<const float4*>(&A[(size_t)(m0 + row) * K + kn + c4 * 4]);
                else
                    pa[r] = make_float4(0.f, 0.f, 0.f, 0.f);
                int brow = id >> 5, bc4 = id & 31;
                pb[r] = *reinterpret_cast<const float4*>(&B[(size_t)(kn + brow) * NPIXL + n0 + bc4 * 4]);
            }
        }
        #pragma unroll
        for (int kk = 0; kk < 16; kk++) {
            float a[8], b[8];
            float4 t0 = *reinterpret_cast<const float4*>(&As[kk][tm * 8]);
            float4 t1 = *reinterpret_cast<const float4*>(&As[kk][tm * 8 + 4]);
            a[0]=t0.x; a[1]=t0.y; a[2]=t0.z; a[3]=t0.w;
            a[4]=t1.x; a[5]=t1.y; a[6]=t1.z; a[7]=t1.w;
            float4 u0 = *reinterpret_cast<const float4*>(&Bs[kk][tn * 8]);
            float4 u1 = *reinterpret_cast<const float4*>(&Bs[kk][tn * 8 + 4]);
            b[0]=u0.x; b[1]=u0.y; b[2]=u0.z; b[3]=u0.w;
            b[4]=u1.x; b[5]=u1.y; b[6]=u1.z; b[7]=u1.w;
            #pragma unroll
            for (int i = 0; i < 8; i++)
                #pragma unroll
                for (int j = 0; j < 8; j++)
                    acc[i][j] += a[i] * b[j];
        }
        __syncthreads();
        if (has_next) {
            #pragma unroll
            for (int r = 0; r < 2; r++) {
                int id = tid + r * 256;
                int row = id >> 2, c4 = id & 3;
                As[c4 * 4 + 0][row] = pa[r].x;
                As[c4 * 4 + 1][row] = pa[r].y;
                As[c4 * 4 + 2][row] = pa[r].z;
                As[c4 * 4 + 3][row] = pa[r].w;
                int brow = id >> 5, bc4 = id & 31;
                *reinterpret_cast<float4*>(&Bs[brow][bc4 * 4]) = pb[r];
            }
            __syncthreads();
        }
    }

    // ---------------- epilogue ----------------
    const int mb = m0 + tm * 8;
    float scale[8], bias[8];
    #pragma unroll
    for (int i = 0; i < 8; i++) {
        int mg = mb + i;
        if (mode == 1) {
            scale[i] = 1.f;
            bias[i]  = (mg < M) ? bb[mg] : 0.f;
        } else {
            float s  = gg[mg] / sqrtf(vv[mg] + 1e-5f);
            scale[i] = s;
            bias[i]  = bb[mg] - mm[mg] * s;
        }
    }
    #pragma unroll
    for (int i = 0; i < 8; i++) {
        int mg = mb + i;
        if (mg >= M) continue;
        #pragma unroll
        for (int j = 0; j < 8; j++) {
            int ng = n0 + tn * 8 + j;
            float v = acc[i][j] * scale[i] + bias[i];
            if (mode == 0) {
                C[(size_t)mg * NPIXL + ng] = fmaxf(v, 0.f);
            } else if (mode == 1) {
                C[(size_t)mg * NPIXL + ng] = v;
            } else if (mode == 2) {
                size_t o = (size_t)mg * NPIXL + ng;
                C[o] = C[o] + fmaxf(v, 0.f);
            } else {
                int bi = ng >> 10, pix = ng & 1023;
                size_t o = ((size_t)bi * CH + mg) * (size_t)HW + pix;
                outp[o] = fmaxf(v + resid[o], 0.f);
            }
        }
    }
}

// ---------------- host launcher ----------------
extern "C" void kernel_launch(void* const* d_in, const int* in_sizes, int n_in,
                              void* d_out, int out_size)
{
    (void)in_sizes; (void)n_in; (void)out_size;
    const float* x    = (const float*)d_in[0];
    const float* w1   = (const float*)d_in[1];
    const float* woff = (const float*)d_in[2];
    const float* boff = (const float*)d_in[3];
    const float* w3   = (const float*)d_in[4];
    const float* w2   = (const float*)d_in[5];
    const float* g1 = (const float*)d_in[6];  const float* b1 = (const float*)d_in[7];
    const float* m1 = (const float*)d_in[8];  const float* v1 = (const float*)d_in[9];
    const float* g3 = (const float*)d_in[10]; const float* b3 = (const float*)d_in[11];
    const float* m3 = (const float*)d_in[12]; const float* v3 = (const float*)d_in[13];
    const float* g2 = (const float*)d_in[14]; const float* b2 = (const float*)d_in[15];
    const float* m2 = (const float*)d_in[16]; const float* v2 = (const float*)d_in[17];
    float* out = (float*)d_out;

    float *col3, *col2, *cold, *osum, *offp;
    cudaGetSymbolAddress((void**)&col3, g_col3);
    cudaGetSymbolAddress((void**)&col2, g_col2);
    cudaGetSymbolAddress((void**)&cold, g_cold);
    cudaGetSymbolAddress((void**)&osum, g_osum);
    cudaGetSymbolAddress((void**)&offp, g_offs);

    const int nblk_i2c = (int)((2304ULL * NPIXL + 255) / 256);

    // 1) im2col of x (shared by conv1 and offset conv)
    im2col3_kernel<<<nblk_i2c, 256>>>(x, col3, 0);

    // 2) conv1 -> bn1 -> relu  into g_osum
    gemm_kernel<<<dim3(256, 2), 256>>>(w1, col3, osum, 256, 2304, 0,
                                       g1, b1, m1, v1, nullptr, nullptr);

    // 3) offset conv (+ bias) into g_offs
    gemm_kernel<<<dim3(256, 1), 256>>>(woff, col3, offp, 50, 2304, 1,
                                       nullptr, boff, nullptr, nullptr, nullptr, nullptr);

    // 4) deformable bilinear sampling -> g_cold
    deform_sample_kernel<<<dim3(32, 25), 256>>>(x);

    // 5) deform conv -> bn3 -> relu, accumulate into g_osum
    gemm_kernel<<<dim3(256, 2), 256>>>(w3, cold, osum, 256, 6400, 2,
                                       g3, b3, m3, v3, nullptr, nullptr);

    // 6) im2col of g_osum (channel-major layout)
    im2col3_kernel<<<nblk_i2c, 256>>>(osum, col2, 1);

    // 7) conv2 -> bn2 -> +x residual -> relu -> d_out (NCHW)
    gemm_kernel<<<dim3(256, 2), 256>>>(w2, col2, nullptr, 256, 2304, 3,
                                       g2, b2, m2, v2, x, out);
}

// round 8
// speedup vs baseline: 1.2811x; 1.2811x over previous
#include <cuda_runtime.h>
#include <math.h>
#include <stdint.h>

// ---------------- problem constants ----------------
#define BATCH 32
#define CH    256
#define HW    1024
#define NPIX  32768
#define NPIXL 32768ULL

// ---------------- static device scratch ----------------
__device__ float g_col3[2304ULL * NPIXL];   // im2col of x (3x3, pad1)        [K][NPIX]
__device__ float g_col2[2304ULL * NPIXL];   // im2col of out_sum (3x3, pad1)  [K][NPIX]
__device__ float g_cold[6400ULL * NPIXL];   // deform im2col (5x5)            [K][NPIX]
__device__ float g_osum[256ULL  * NPIXL];   // relu(bn(conv1)) += relu(bn(deform))
__device__ float g_offs[50ULL   * NPIXL];   // offset field [50][NPIX]

// ---------------- PTX helpers (sm_80-era only: legal on plain sm_103) --------
__device__ __forceinline__ uint32_t smem_u32(const void* p) {
    uint32_t a;
    asm("{ .reg .u64 t; cvta.to.shared.u64 t, %1; cvt.u32.u64 %0, t; }" : "=r"(a) : "l"(p));
    return a;
}
#define CP_ASYNC16(dst, src) \
    asm volatile("cp.async.cg.shared.global [%0], [%1], 16;" :: "r"(dst), "l"(src))
#define CP_COMMIT()  asm volatile("cp.async.commit_group;" ::: "memory")
#define CP_WAIT0()   asm volatile("cp.async.wait_group 0;" ::: "memory")
#define CP_WAIT1()   asm volatile("cp.async.wait_group 1;" ::: "memory")

// mma.sync m16n8k8 tf32: A/B are .b32 (tf32 bits), C/D fp32
__device__ __forceinline__ void mma1688(float* c, const uint32_t* a, const uint32_t* b) {
    asm volatile(
        "mma.sync.aligned.m16n8k8.row.col.f32.tf32.tf32.f32 "
        "{%0,%1,%2,%3}, {%4,%5,%6,%7}, {%8,%9}, {%0,%1,%2,%3};"
        : "+f"(c[0]), "+f"(c[1]), "+f"(c[2]), "+f"(c[3])
        : "r"(a[0]), "r"(a[1]), "r"(a[2]), "r"(a[3]), "r"(b[0]), "r"(b[1]));
}

// split fp32 -> (tf32 hi, tf32 lo):  hi = rna(v), lo = rna(v - hi)
__device__ __forceinline__ void tf32_split(float v, uint32_t& hi, uint32_t& lo) {
    asm("cvt.rna.tf32.f32 %0, %1;" : "=r"(hi) : "f"(v));
    float l = v - __uint_as_float(hi);
    asm("cvt.rna.tf32.f32 %0, %1;" : "=r"(lo) : "f"(l));
}

// ---------------- im2col for 3x3 / pad 1 ----------------
__global__ void im2col3_kernel(const float* __restrict__ src,
                               float* __restrict__ dst, int layout)
{
    size_t idx = (size_t)blockIdx.x * blockDim.x + threadIdx.x;
    if (idx >= 2304ULL * NPIXL) return;
    int row = (int)(idx >> 15);
    int n   = (int)(idx & 32767);
    int c = row / 9, t = row % 9;
    int ky = t / 3, kx = t % 3;
    int b = n >> 10, pix = n & 1023;
    int ho = pix >> 5, wo = pix & 31;
    int iy = ho + ky - 1, ix = wo + kx - 1;
    float v = 0.f;
    if ((unsigned)iy < 32u && (unsigned)ix < 32u) {
        size_t s = (layout == 0)
            ? (((size_t)(b * CH + c)) << 10) + (size_t)(iy * 32 + ix)
            : (((size_t)c) << 15) + (size_t)((b << 10) + iy * 32 + ix);
        v = src[s];
    }
    dst[idx] = v;
}

// ---------------- deformable bilinear sampling ----------------
__global__ void deform_sample_kernel(const float* __restrict__ x)
{
    int b = blockIdx.x;          // 32
    int k = blockIdx.y;          // 25
    int i = k / 5, j = k % 5;
    int tid = threadIdx.x;       // 256
    const float* xb = x + (size_t)b * CH * HW;

    int   offn[4][4];
    float wgt [4][4];
    int   nn  [4];
    #pragma unroll
    for (int q = 0; q < 4; q++) {
        int p  = tid + q * 256;
        int ho = p >> 5, wo = p & 31;
        int n  = (b << 10) + p;
        nn[q]  = n;
        float dy = g_offs[(size_t)(2 * k)     * NPIXL + n];
        float dx = g_offs[(size_t)(2 * k + 1) * NPIXL + n];
        float py = (float)(ho - 2 + i) + dy;
        float px = (float)(wo - 2 + j) + dx;
        float y0 = floorf(py), x0 = floorf(px);
        float wy1 = py - y0, wx1 = px - x0;
        float wy0 = 1.f - wy1, wx0 = 1.f - wx1;
        float ys[2]  = {y0, y0 + 1.f};
        float xs[2]  = {x0, x0 + 1.f};
        float wys[2] = {wy0, wy1};
        float wxs[2] = {wx0, wx1};
        #pragma unroll
        for (int cy = 0; cy < 2; cy++)
            #pragma unroll
            for (int cx = 0; cx < 2; cx++) {
                float yf = ys[cy], xf = xs[cx];
                bool valid = (yf >= 0.f) && (yf <= 31.f) && (xf >= 0.f) && (xf <= 31.f);
                int yc = (int)fminf(fmaxf(yf, 0.f), 31.f);
                int xc = (int)fminf(fmaxf(xf, 0.f), 31.f);
                offn[q][cy * 2 + cx] = yc * 32 + xc;
                wgt [q][cy * 2 + cx] = valid ? wys[cy] * wxs[cx] : 0.f;
            }
    }
    for (int c = 0; c < CH; c++) {
        const float* xc = xb + (size_t)c * HW;
        size_t drow = (size_t)(c * 25 + k) * NPIXL;
        #pragma unroll
        for (int q = 0; q < 4; q++) {
            float v = wgt[q][0] * xc[offn[q][0]] + wgt[q][1] * xc[offn[q][1]]
                    + wgt[q][2] * xc[offn[q][2]] + wgt[q][3] * xc[offn[q][3]];
            g_cold[drow + nn[q]] = v;
        }
    }
}

// ---------------- 3xTF32 mma.sync GEMM: C[M,NPIX] = A[M,K]*B[K,NPIX] --------
// Block 128x128, 4 warps, warp tile 64x64, BK=16, cp.async double-buffered B,
// register-staged A transpose. Each operand split hi/lo (tf32); accumulate
// hi*hi + hi*lo + lo*hi for ~fp32 accuracy.
// modes: 0 C=relu(bn)   1 C=acc+bias   2 C+=relu(bn)   3 out=relu(bn+resid) NCHW
#define BK 16
#define SROW 136   // smem row stride (floats): conflict-free frag access

__global__ __launch_bounds__(128)
void gemm_mma(const float* __restrict__ A, const float* __restrict__ B,
              float* __restrict__ C, int M, int K, int mode,
              const float* __restrict__ gg, const float* __restrict__ bb,
              const float* __restrict__ mm, const float* __restrict__ vv,
              const float* __restrict__ resid, float* __restrict__ outp)
{
    __shared__ float As[2][BK][SROW];
    __shared__ float Bs[2][BK][SROW];

    const int tid  = threadIdx.x;
    const int wid  = tid >> 5;
    const int lane = tid & 31;
    const int lr   = lane >> 2;      // fragment row group 0..7
    const int lc   = lane & 3;       // fragment k group 0..3
    const int m0   = blockIdx.y * 128;
    const int n0   = blockIdx.x * 128;
    const int wm   = (wid & 1) * 64;
    const int wn   = (wid >> 1) * 64;

    float c[4][8][4];
    #pragma unroll
    for (int i = 0; i < 4; i++)
        #pragma unroll
        for (int j = 0; j < 8; j++)
            #pragma unroll
            for (int q = 0; q < 4; q++) c[i][j][q] = 0.f;

    const int nt = K >> 4;   // K/16 tiles
    const int am = m0 + tid; // A row handled by this thread
    const bool aok = (am < M);
    const float* arow = A + (size_t)(aok ? am : 0) * K;

    // ---- B tile cp.async: 512 float4, 4 per thread ----
    auto issueB = [&](int it, int buf) {
        const int kt = it << 4;
        #pragma unroll
        for (int q = 0; q < 4; q++) {
            int f   = tid + (q << 7);
            int k   = f >> 5, nf4 = (f & 31) << 2;
            uint32_t dst = smem_u32(&Bs[buf][k][nf4]);
            const float* src = &B[(size_t)(kt + k) * NPIXL + n0 + nf4];
            CP_ASYNC16(dst, src);
        }
        CP_COMMIT();
    };
    // ---- A tile: ldg 4 float4 along K into regs ----
    float4 ar[4];
    auto loadA = [&](int it) {
        const int kt = it << 4;
        #pragma unroll
        for (int q = 0; q < 4; q++)
            ar[q] = aok ? *reinterpret_cast<const float4*>(&arow[kt + (q << 2)])
                        : make_float4(0.f, 0.f, 0.f, 0.f);
    };
    auto storeA = [&](int buf) {
        #pragma unroll
        for (int q = 0; q < 4; q++) {
            As[buf][(q << 2) + 0][tid] = ar[q].x;
            As[buf][(q << 2) + 1][tid] = ar[q].y;
            As[buf][(q << 2) + 2][tid] = ar[q].z;
            As[buf][(q << 2) + 3][tid] = ar[q].w;
        }
    };

    // prologue: tile 0
    loadA(0); storeA(0);
    issueB(0, 0);

    for (int it = 0; it < nt; it++) {
        const int buf = it & 1;
        const bool nxt = (it + 1) < nt;
        if (nxt) { issueB(it + 1, buf ^ 1); loadA(it + 1); }
        if (nxt) CP_WAIT1(); else CP_WAIT0();
        __syncthreads();

        #pragma unroll
        for (int ks = 0; ks < 2; ks++) {
            const int kb = ks << 3;
            uint32_t ah[4][4], alo[4][4];
            #pragma unroll
            for (int mf = 0; mf < 4; mf++) {
                const int mb = wm + (mf << 4) + lr;
                tf32_split(As[buf][kb + lc    ][mb    ], ah[mf][0], alo[mf][0]);
                tf32_split(As[buf][kb + lc    ][mb + 8], ah[mf][1], alo[mf][1]);
                tf32_split(As[buf][kb + 4 + lc][mb    ], ah[mf][2], alo[mf][2]);
                tf32_split(As[buf][kb + 4 + lc][mb + 8], ah[mf][3], alo[mf][3]);
            }
            #pragma unroll
            for (int nf = 0; nf < 8; nf++) {
                const int nb = wn + (nf << 3) + lr;
                uint32_t bh[2], bl[2];
                tf32_split(Bs[buf][kb + lc    ][nb], bh[0], bl[0]);
                tf32_split(Bs[buf][kb + 4 + lc][nb], bh[1], bl[1]);
                #pragma unroll
                for (int mf = 0; mf < 4; mf++) {
                    mma1688(c[mf][nf], ah[mf],  bh);
                    mma1688(c[mf][nf], ah[mf],  bl);
                    mma1688(c[mf][nf], alo[mf], bh);
                }
            }
        }
        if (nxt) storeA(buf ^ 1);
        __syncthreads();
    }

    // ---------------- epilogue (registers -> global) ----------------
    #pragma unroll
    for (int mf = 0; mf < 4; mf++) {
        const int r0 = m0 + wm + (mf << 4) + lr;
        const int r1 = r0 + 8;
        float sc0 = 1.f, bi0 = 0.f, sc1 = 1.f, bi1 = 0.f;
        if (mode == 1) {
            if (r0 < M) bi0 = bb[r0];
            if (r1 < M) bi1 = bb[r1];
        } else {
            float s0 = gg[r0] * rsqrtf(vv[r0] + 1e-5f);
            float s1 = gg[r1] * rsqrtf(vv[r1] + 1e-5f);
            sc0 = s0; bi0 = bb[r0] - mm[r0] * s0;
            sc1 = s1; bi1 = bb[r1] - mm[r1] * s1;
        }
        #pragma unroll
        for (int nf = 0; nf < 8; nf++) {
            const int nc = n0 + wn + (nf << 3) + (lc << 1);
            float v0 = c[mf][nf][0] * sc0 + bi0;
            float v1 = c[mf][nf][1] * sc0 + bi0;
            float v2 = c[mf][nf][2] * sc1 + bi1;
            float v3 = c[mf][nf][3] * sc1 + bi1;
            if (mode == 0 || mode == 2) {
                v0 = fmaxf(v0, 0.f); v1 = fmaxf(v1, 0.f);
                v2 = fmaxf(v2, 0.f); v3 = fmaxf(v3, 0.f);
            }
            if (mode == 3) {
                const int bidx = n0 >> 10;
                const int pix  = nc & 1023;
                if (r0 < M) {
                    size_t o = ((size_t)(bidx * CH + r0) << 10) + pix;
                    float2 rs = *reinterpret_cast<const float2*>(&resid[o]);
                    float2 w;
                    w.x = fmaxf(v0 + rs.x, 0.f);
                    w.y = fmaxf(v1 + rs.y, 0.f);
                    *reinterpret_cast<float2*>(&outp[o]) = w;
                }
                if (r1 < M) {
                    size_t o = ((size_t)(bidx * CH + r1) << 10) + pix;
                    float2 rs = *reinterpret_cast<const float2*>(&resid[o]);
                    float2 w;
                    w.x = fmaxf(v2 + rs.x, 0.f);
                    w.y = fmaxf(v3 + rs.y, 0.f);
                    *reinterpret_cast<float2*>(&outp[o]) = w;
                }
            } else if (mode == 2) {
                if (r0 < M) {
                    size_t o = (size_t)r0 * NPIXL + nc;
                    float2 p = *reinterpret_cast<const float2*>(&C[o]);
                    p.x += v0; p.y += v1;
                    *reinterpret_cast<float2*>(&C[o]) = p;
                }
                if (r1 < M) {
                    size_t o = (size_t)r1 * NPIXL + nc;
                    float2 p = *reinterpret_cast<const float2*>(&C[o]);
                    p.x += v2; p.y += v3;
                    *reinterpret_cast<float2*>(&C[o]) = p;
                }
            } else {
                if (r0 < M) {
                    float2 w; w.x = v0; w.y = v1;
                    *reinterpret_cast<float2*>(&C[(size_t)r0 * NPIXL + nc]) = w;
                }
                if (r1 < M) {
                    float2 w; w.x = v2; w.y = v3;
                    *reinterpret_cast<float2*>(&C[(size_t)r1 * NPIXL + nc]) = w;
                }
            }
        }
    }
}

// ---------------- host launcher ----------------
extern "C" void kernel_launch(void* const* d_in, const int* in_sizes, int n_in,
                              void* d_out, int out_size)
{
    (void)in_sizes; (void)n_in; (void)out_size;
    const float* x    = (const float*)d_in[0];
    const float* w1   = (const float*)d_in[1];
    const float* woff = (const float*)d_in[2];
    const float* boff = (const float*)d_in[3];
    const float* w3   = (const float*)d_in[4];
    const float* w2   = (const float*)d_in[5];
    const float* g1 = (const float*)d_in[6];  const float* b1 = (const float*)d_in[7];
    const float* m1 = (const float*)d_in[8];  const float* v1 = (const float*)d_in[9];
    const float* g3 = (const float*)d_in[10]; const float* b3 = (const float*)d_in[11];
    const float* m3 = (const float*)d_in[12]; const float* v3 = (const float*)d_in[13];
    const float* g2 = (const float*)d_in[14]; const float* b2 = (const float*)d_in[15];
    const float* m2 = (const float*)d_in[16]; const float* v2 = (const float*)d_in[17];
    float* out = (float*)d_out;

    float *col3, *col2, *cold, *osum, *offp;
    cudaGetSymbolAddress((void**)&col3, g_col3);
    cudaGetSymbolAddress((void**)&col2, g_col2);
    cudaGetSymbolAddress((void**)&cold, g_cold);
    cudaGetSymbolAddress((void**)&osum, g_osum);
    cudaGetSymbolAddress((void**)&offp, g_offs);

    const int nblk_i2c = (int)((2304ULL * NPIXL + 255) / 256);

    // 1) im2col of x (shared by conv1 and offset conv)
    im2col3_kernel<<<nblk_i2c, 256>>>(x, col3, 0);

    // 2) conv1 -> bn1 -> relu  into g_osum
    gemm_mma<<<dim3(256, 2), 128>>>(w1, col3, osum, 256, 2304, 0,
                                    g1, b1, m1, v1, nullptr, nullptr);

    // 3) offset conv (+ bias) into g_offs
    gemm_mma<<<dim3(256, 1), 128>>>(woff, col3, offp, 50, 2304, 1,
                                    nullptr, boff, nullptr, nullptr, nullptr, nullptr);

    // 4) deformable bilinear sampling -> g_cold
    deform_sample_kernel<<<dim3(32, 25), 256>>>(x);

    // 5) deform conv -> bn3 -> relu, accumulate into g_osum
    gemm_mma<<<dim3(256, 2), 128>>>(w3, cold, osum, 256, 6400, 2,
                                    g3, b3, m3, v3, nullptr, nullptr);

    // 6) im2col of g_osum (channel-major layout)
    im2col3_kernel<<<nblk_i2c, 256>>>(osum, col2, 1);

    // 7) conv2 -> bn2 -> +x residual -> relu -> d_out (NCHW)
    gemm_mma<<<dim3(256, 2), 128>>>(w2, col2, nullptr, 256, 2304, 3,
                                    g2, b2, m2, v2, x, out);
}